// round 1
// baseline (speedup 1.0000x reference)
#include <cuda_runtime.h>
#include <math.h>

#define EMB    768
#define HEADS  12
#define DEPTH  64
#define BATCH  2
#define SEQ    4096
#define MROWS  (BATCH * SEQ)   // 8192

// Scratch (allocation-free): Q, K, V, attention output, all [B, S, E] row-major.
__device__ float g_Q[MROWS * EMB];
__device__ float g_K[MROWS * EMB];
__device__ float g_V[MROWS * EMB];
__device__ float g_O[MROWS * EMB];

// ---------------------------------------------------------------------------
// NT SGEMM tile body: C[m,n] = sum_k A[m,k] * W[n,k] (+ bias[n])
// M blocks on y, N blocks on x. BM=BN=128, BK=16, 256 threads, 8x8 micro-tile
// with 16-strided row/col mapping (conflict-free smem reads, coalesced writes).
// ---------------------------------------------------------------------------
__device__ __forceinline__ void sgemm_body(const float* __restrict__ A,
                                           const float* __restrict__ W,
                                           float*       __restrict__ C,
                                           const float* __restrict__ bias)
{
    __shared__ float As[16][132];
    __shared__ float Ws[16][132];

    const int tid  = threadIdx.x;
    const int tm   = tid >> 4;          // 0..15
    const int tn   = tid & 15;          // 0..15
    const int row0 = blockIdx.y * 128;
    const int col0 = blockIdx.x * 128;

    float acc[8][8];
#pragma unroll
    for (int i = 0; i < 8; i++)
#pragma unroll
        for (int j = 0; j < 8; j++) acc[i][j] = 0.f;

    for (int k0 = 0; k0 < EMB; k0 += 16) {
        // Load 128x16 tiles of A and W (transposed into [k][m] layout).
#pragma unroll
        for (int l = 0; l < 2; l++) {
            int slot = tid + l * 256;       // 0..511 float4 slots
            int r    = slot >> 2;           // row 0..127
            int c4   = (slot & 3) << 2;     // k offset 0,4,8,12
            float4 av = *(const float4*)(A + (row0 + r) * EMB + k0 + c4);
            As[c4 + 0][r] = av.x; As[c4 + 1][r] = av.y;
            As[c4 + 2][r] = av.z; As[c4 + 3][r] = av.w;
            float4 wv = *(const float4*)(W + (col0 + r) * EMB + k0 + c4);
            Ws[c4 + 0][r] = wv.x; Ws[c4 + 1][r] = wv.y;
            Ws[c4 + 2][r] = wv.z; Ws[c4 + 3][r] = wv.w;
        }
        __syncthreads();

#pragma unroll
        for (int k = 0; k < 16; k++) {
            float a[8], b[8];
#pragma unroll
            for (int i = 0; i < 8; i++) a[i] = As[k][tm + 16 * i];
#pragma unroll
            for (int j = 0; j < 8; j++) b[j] = Ws[k][tn + 16 * j];
#pragma unroll
            for (int i = 0; i < 8; i++)
#pragma unroll
                for (int j = 0; j < 8; j++)
                    acc[i][j] = fmaf(a[i], b[j], acc[i][j]);
        }
        __syncthreads();
    }

#pragma unroll
    for (int i = 0; i < 8; i++) {
        int r = row0 + tm + 16 * i;
#pragma unroll
        for (int j = 0; j < 8; j++) {
            int c = col0 + tn + 16 * j;
            float v = acc[i][j];
            if (bias) v += bias[c];
            C[r * EMB + c] = v;
        }
    }
}

// QKV projection: blockIdx.z selects which of Q/K/V to compute.
__global__ __launch_bounds__(256) void qkv_kernel(const float* __restrict__ x,
                                                  const float* __restrict__ Wq,
                                                  const float* __restrict__ Wk,
                                                  const float* __restrict__ Wv)
{
    const float* W = (blockIdx.z == 0) ? Wq : (blockIdx.z == 1) ? Wk : Wv;
    float*       C = (blockIdx.z == 0) ? g_Q : (blockIdx.z == 1) ? g_K : g_V;
    sgemm_body(x, W, C, nullptr);
}

// Output projection with bias.
__global__ __launch_bounds__(256) void proj_kernel(const float* __restrict__ Wo,
                                                   const float* __restrict__ bo,
                                                   float* __restrict__ out)
{
    sgemm_body(g_O, Wo, out, bo);
}

// ---------------------------------------------------------------------------
// Flash attention: one CTA = (64-query tile, head, batch). 256 threads as a
// 16x16 grid; each thread owns 4 rows (ty+16i) x 4 cols (tx+16j).
// Online softmax, warp-shuffle row reductions (tx lives in lane bits 0..3).
// K smem tile is reused as the P (probability) tile.
// ---------------------------------------------------------------------------
#define ATTN_SMEM ((64 * 64 + 64 * 65 + 64 * 64) * 4)   // Qs + K/P + Vs = 49408 B

__global__ __launch_bounds__(256) void attn_kernel()
{
    extern __shared__ float sm[];
    float* Qs  = sm;                 // [64][64]
    float* KPs = sm + 64 * 64;       // [64][65]  K tile, reused for P
    float* Vs  = KPs + 64 * 65;      // [64][64]

    const int b  = blockIdx.z;
    const int h  = blockIdx.y;
    const int qt = blockIdx.x;
    const int tid = threadIdx.x;
    const int ty  = tid >> 4;        // 0..15
    const int tx  = tid & 15;        // 0..15

    // Load Q tile once.
    const float* Qg = g_Q + (b * SEQ + qt * 64) * EMB + h * DEPTH;
    for (int l = tid; l < 64 * 64; l += 256) {
        int r = l >> 6, c = l & 63;
        Qs[r * 64 + c] = Qg[r * EMB + c];
    }

    float m[4], lsum[4], o[4][4];
#pragma unroll
    for (int i = 0; i < 4; i++) {
        m[i] = -1e30f; lsum[i] = 0.f;
#pragma unroll
        for (int j = 0; j < 4; j++) o[i][j] = 0.f;
    }
    __syncthreads();

    for (int kt = 0; kt < SEQ / 64; kt++) {
        const float* Kg = g_K + (b * SEQ + kt * 64) * EMB + h * DEPTH;
        const float* Vg = g_V + (b * SEQ + kt * 64) * EMB + h * DEPTH;
        for (int l = tid; l < 64 * 64; l += 256) {
            int r = l >> 6, c = l & 63;
            KPs[r * 65 + c] = Kg[r * EMB + c];
            Vs [r * 64 + c] = Vg[r * EMB + c];
        }
        __syncthreads();

        // S = Q K^T  (4x4 per thread)
        float sacc[4][4];
#pragma unroll
        for (int i = 0; i < 4; i++)
#pragma unroll
            for (int j = 0; j < 4; j++) sacc[i][j] = 0.f;

#pragma unroll 4
        for (int d = 0; d < 64; d++) {
            float qv[4], kv[4];
#pragma unroll
            for (int i = 0; i < 4; i++) qv[i] = Qs[(ty + 16 * i) * 64 + d];
#pragma unroll
            for (int j = 0; j < 4; j++) kv[j] = KPs[(tx + 16 * j) * 65 + d];
#pragma unroll
            for (int i = 0; i < 4; i++)
#pragma unroll
                for (int j = 0; j < 4; j++)
                    sacc[i][j] = fmaf(qv[i], kv[j], sacc[i][j]);
        }
        __syncthreads();   // done reading K; KPs may be overwritten with P

        // Online softmax (per row), write P into KPs.
        float corr[4];
#pragma unroll
        for (int i = 0; i < 4; i++) {
            float mx = -1e30f;
#pragma unroll
            for (int j = 0; j < 4; j++) {
                sacc[i][j] *= 0.125f;               // 1/sqrt(DEPTH)
                mx = fmaxf(mx, sacc[i][j]);
            }
#pragma unroll
            for (int ofs = 8; ofs >= 1; ofs >>= 1)  // reduce over tx (lane bits 0..3)
                mx = fmaxf(mx, __shfl_xor_sync(0xffffffffu, mx, ofs));
            float mnew = fmaxf(m[i], mx);
            float c0   = expf(m[i] - mnew);
            float psum = 0.f;
#pragma unroll
            for (int j = 0; j < 4; j++) {
                float p = expf(sacc[i][j] - mnew);
                KPs[(ty + 16 * i) * 65 + tx + 16 * j] = p;
                psum += p;
            }
#pragma unroll
            for (int ofs = 8; ofs >= 1; ofs >>= 1)
                psum += __shfl_xor_sync(0xffffffffu, psum, ofs);
            lsum[i] = lsum[i] * c0 + psum;
            m[i]    = mnew;
            corr[i] = c0;
        }
#pragma unroll
        for (int i = 0; i < 4; i++)
#pragma unroll
            for (int j = 0; j < 4; j++) o[i][j] *= corr[i];
        __syncthreads();   // P fully written

        // O += P V  (4x4 per thread; d columns = tx+16j)
#pragma unroll 4
        for (int c = 0; c < 64; c++) {
            float pv[4], vv[4];
#pragma unroll
            for (int i = 0; i < 4; i++) pv[i] = KPs[(ty + 16 * i) * 65 + c];
#pragma unroll
            for (int j = 0; j < 4; j++) vv[j] = Vs[c * 64 + tx + 16 * j];
#pragma unroll
            for (int i = 0; i < 4; i++)
#pragma unroll
                for (int j = 0; j < 4; j++)
                    o[i][j] = fmaf(pv[i], vv[j], o[i][j]);
        }
        __syncthreads();   // done reading P/V before next tile load
    }

    // Normalize and write out in [B, S, E] layout.
    float* Og = g_O + (b * SEQ + qt * 64) * EMB + h * DEPTH;
#pragma unroll
    for (int i = 0; i < 4; i++) {
        float inv = 1.f / lsum[i];
#pragma unroll
        for (int j = 0; j < 4; j++)
            Og[(ty + 16 * i) * EMB + tx + 16 * j] = o[i][j] * inv;
    }
}

// ---------------------------------------------------------------------------
extern "C" void kernel_launch(void* const* d_in, const int* in_sizes, int n_in,
                              void* d_out, int out_size)
{
    const float* x  = (const float*)d_in[0];
    const float* Wq = (const float*)d_in[1];
    const float* Wk = (const float*)d_in[2];
    const float* Wv = (const float*)d_in[3];
    const float* Wo = (const float*)d_in[4];
    const float* bo = (const float*)d_in[5];
    float* out = (float*)d_out;

    cudaFuncSetAttribute(attn_kernel,
                         cudaFuncAttributeMaxDynamicSharedMemorySize, ATTN_SMEM);

    // 1) Q/K/V projections: 6x64 tile grid, z selects weight.
    qkv_kernel<<<dim3(6, 64, 3), 256>>>(x, Wq, Wk, Wv);

    // 2) Flash attention over 64-query tiles.
    attn_kernel<<<dim3(SEQ / 64, HEADS, BATCH), 256, ATTN_SMEM>>>();

    // 3) Output projection + bias.
    proj_kernel<<<dim3(6, 64, 1), 256>>>(Wo, bo, out);
}

// round 7
// speedup vs baseline: 2.9137x; 2.9137x over previous
#include <cuda_runtime.h>
#include <cuda_bf16.h>
#include <math.h>
#include <stdint.h>

#define EMB    768
#define HEADS  12
#define DEPTH  64
#define BATCH  2
#define SEQ    4096
#define MROWS  (BATCH * SEQ)      // 8192
#define BH     (BATCH * HEADS)    // 24

typedef unsigned int  u32;
typedef unsigned short u16;

// ---------------------------------------------------------------------------
// Scratch (allocation-free device globals), all bf16 hi/lo split pairs.
// ---------------------------------------------------------------------------
__device__ u16 g_xh[MROWS * EMB],  g_xl[MROWS * EMB];
__device__ u16 g_Wqh[EMB * EMB],   g_Wql[EMB * EMB];
__device__ u16 g_Wkh[EMB * EMB],   g_Wkl[EMB * EMB];
__device__ u16 g_Wvh[EMB * EMB],   g_Wvl[EMB * EMB];
__device__ u16 g_Woh[EMB * EMB],   g_Wol[EMB * EMB];
__device__ u16 g_Qh[MROWS * EMB],  g_Ql[MROWS * EMB];   // Q pre-scaled by 0.125
__device__ u16 g_Kh[MROWS * EMB],  g_Kl[MROWS * EMB];
__device__ u16 g_Vh[MROWS * EMB],  g_Vl[MROWS * EMB];
__device__ u16 g_Vth[BH * DEPTH * SEQ], g_Vtl[BH * DEPTH * SEQ]; // V^T [bh][d][s]
__device__ u16 g_Oh[MROWS * EMB],  g_Ol[MROWS * EMB];

// ---------------------------------------------------------------------------
// Helpers
// ---------------------------------------------------------------------------
__device__ __forceinline__ void split1(float v, u16& h, u16& l) {
    __nv_bfloat16 hb = __float2bfloat16(v);
    __nv_bfloat16 lb = __float2bfloat16(v - __bfloat162float(hb));
    h = __bfloat16_as_ushort(hb);
    l = __bfloat16_as_ushort(lb);
}
// pack two split values into bf16x2 regs (low half = v0, high = v1)
__device__ __forceinline__ void split2(float v0, float v1, u32& h, u32& l) {
    u16 h0, l0, h1, l1;
    split1(v0, h0, l0); split1(v1, h1, l1);
    h = (u32)h0 | ((u32)h1 << 16);
    l = (u32)l0 | ((u32)l1 << 16);
}

// m16n8k16 row.col bf16 mma, fp32 accumulate (base-ISA, sm_80+)
__device__ __forceinline__ void mma16816(float* c, const u32* a, const u32* b) {
    asm volatile(
        "mma.sync.aligned.m16n8k16.row.col.f32.bf16.bf16.f32 "
        "{%0,%1,%2,%3}, {%4,%5,%6,%7}, {%8,%9}, {%0,%1,%2,%3};"
        : "+f"(c[0]), "+f"(c[1]), "+f"(c[2]), "+f"(c[3])
        : "r"(a[0]), "r"(a[1]), "r"(a[2]), "r"(a[3]), "r"(b[0]), "r"(b[1]));
}

// ---------------------------------------------------------------------------
// 1) fp32 -> bf16 hi/lo elementwise convert
// ---------------------------------------------------------------------------
__global__ __launch_bounds__(256) void convert_kernel(const float* __restrict__ src,
                                                      u16* __restrict__ dh,
                                                      u16* __restrict__ dl, int n)
{
    int i = (blockIdx.x * 256 + threadIdx.x) * 4;
    if (i >= n) return;
    float4 v = *(const float4*)(src + i);
    u16 h0,l0,h1,l1,h2,l2,h3,l3;
    split1(v.x,h0,l0); split1(v.y,h1,l1); split1(v.z,h2,l2); split1(v.w,h3,l3);
    *(uint2*)(dh + i) = make_uint2((u32)h0 | ((u32)h1<<16), (u32)h2 | ((u32)h3<<16));
    *(uint2*)(dl + i) = make_uint2((u32)l0 | ((u32)l1<<16), (u32)l2 | ((u32)l3<<16));
}

// Fused convert of the four 768x768 weight matrices (y selects which).
__global__ __launch_bounds__(256) void convert_w_kernel(const float* __restrict__ Wq,
                                                        const float* __restrict__ Wk,
                                                        const float* __restrict__ Wv,
                                                        const float* __restrict__ Wo)
{
    const float* src; u16 *dh, *dl;
    switch (blockIdx.y) {
        case 0:  src = Wq; dh = g_Wqh; dl = g_Wql; break;
        case 1:  src = Wk; dh = g_Wkh; dl = g_Wkl; break;
        case 2:  src = Wv; dh = g_Wvh; dl = g_Wvl; break;
        default: src = Wo; dh = g_Woh; dl = g_Wol; break;
    }
    int i = (blockIdx.x * 256 + threadIdx.x) * 4;
    if (i >= EMB * EMB) return;
    float4 v = *(const float4*)(src + i);
    u16 h0,l0,h1,l1,h2,l2,h3,l3;
    split1(v.x,h0,l0); split1(v.y,h1,l1); split1(v.z,h2,l2); split1(v.w,h3,l3);
    *(uint2*)(dh + i) = make_uint2((u32)h0 | ((u32)h1<<16), (u32)h2 | ((u32)h3<<16));
    *(uint2*)(dl + i) = make_uint2((u32)l0 | ((u32)l1<<16), (u32)l2 | ((u32)l3<<16));
}

// ---------------------------------------------------------------------------
// 2) 128x128 GEMM tile via mma.sync, split-3 bf16.  C[m,n] = sum_k A[m,k]W[n,k]
//    256 threads = 8 warps (4 m-warps x 2 n-warps); warp = 32 rows x 64 cols.
// ---------------------------------------------------------------------------
#define GS_PAD 72                          // u16 elems per smem row (144 B)
#define G_TILE (128 * GS_PAD)              // 9216 u16 = 18432 B
#define GEMM_SMEM_BYTES (4 * G_TILE * 2)   // 73728 B

__device__ __forceinline__ void gemm128(const u16* __restrict__ Ah, const u16* __restrict__ Al,
                                        const u16* __restrict__ Wh, const u16* __restrict__ Wl,
                                        int row0, int col0,
                                        int mode, float alpha,
                                        u16* __restrict__ outH, u16* __restrict__ outL,
                                        float* __restrict__ outF, const float* __restrict__ bias)
{
    extern __shared__ char smraw[];
    u16* sAh = (u16*)smraw;
    u16* sAl = sAh + G_TILE;
    u16* sWh = sAl + G_TILE;
    u16* sWl = sWh + G_TILE;

    const int tid  = threadIdx.x;
    const int warp = tid >> 5, lane = tid & 31;
    const int g = lane >> 2, t = lane & 3;
    const int r0  = (warp >> 1) * 32;      // warp row base in tile
    const int c0w = (warp & 1) * 64;       // warp col base in tile

    float acc[2][8][4];
#pragma unroll
    for (int i = 0; i < 2; i++)
#pragma unroll
        for (int n = 0; n < 8; n++)
#pragma unroll
            for (int q = 0; q < 4; q++) acc[i][n][q] = 0.f;

    for (int kc = 0; kc < EMB; kc += 64) {
        // stage 128x64 bf16 tiles (uint4 = 8 bf16; 8 per row)
#pragma unroll
        for (int u = tid; u < 1024; u += 256) {
            int row = u >> 3, q = u & 7;
            size_t ia = (size_t)(row0 + row) * EMB + kc + q * 8;
            size_t iw = (size_t)(col0 + row) * EMB + kc + q * 8;
            *(uint4*)(sAh + row * GS_PAD + q * 8) = *(const uint4*)(Ah + ia);
            *(uint4*)(sAl + row * GS_PAD + q * 8) = *(const uint4*)(Al + ia);
            *(uint4*)(sWh + row * GS_PAD + q * 8) = *(const uint4*)(Wh + iw);
            *(uint4*)(sWl + row * GS_PAD + q * 8) = *(const uint4*)(Wl + iw);
        }
        __syncthreads();

#pragma unroll
        for (int kb = 0; kb < 4; kb++) {
            const int kk = kb * 16 + 2 * t;
            u32 ah[2][4], al[2][4];
#pragma unroll
            for (int i = 0; i < 2; i++) {
                int rb = r0 + 16 * i;
                ah[i][0] = *(const u32*)(sAh + (rb + g    ) * GS_PAD + kk);
                ah[i][1] = *(const u32*)(sAh + (rb + g + 8) * GS_PAD + kk);
                ah[i][2] = *(const u32*)(sAh + (rb + g    ) * GS_PAD + kk + 8);
                ah[i][3] = *(const u32*)(sAh + (rb + g + 8) * GS_PAD + kk + 8);
                al[i][0] = *(const u32*)(sAl + (rb + g    ) * GS_PAD + kk);
                al[i][1] = *(const u32*)(sAl + (rb + g + 8) * GS_PAD + kk);
                al[i][2] = *(const u32*)(sAl + (rb + g    ) * GS_PAD + kk + 8);
                al[i][3] = *(const u32*)(sAl + (rb + g + 8) * GS_PAD + kk + 8);
            }
#pragma unroll
            for (int n = 0; n < 8; n++) {
                int wr = (c0w + 8 * n + g) * GS_PAD;
                u32 bh[2] = { *(const u32*)(sWh + wr + kk), *(const u32*)(sWh + wr + kk + 8) };
                u32 bl[2] = { *(const u32*)(sWl + wr + kk), *(const u32*)(sWl + wr + kk + 8) };
#pragma unroll
                for (int i = 0; i < 2; i++) {
                    mma16816(acc[i][n], ah[i], bh);
                    mma16816(acc[i][n], ah[i], bl);
                    mma16816(acc[i][n], al[i], bh);
                }
            }
        }
        __syncthreads();
    }

    // epilogue: stage fp32 through smem for coalesced output
    float* Cs = (float*)smraw;             // [128][132]
#pragma unroll
    for (int i = 0; i < 2; i++)
#pragma unroll
        for (int n = 0; n < 8; n++) {
            int r = r0 + 16 * i + g, c = c0w + 8 * n + 2 * t;
            *(float2*)(Cs + (r    ) * 132 + c) = make_float2(acc[i][n][0], acc[i][n][1]);
            *(float2*)(Cs + (r + 8) * 132 + c) = make_float2(acc[i][n][2], acc[i][n][3]);
        }
    __syncthreads();

#pragma unroll
    for (int u = tid; u < 128 * 32; u += 256) {
        int r = u >> 5, c4 = (u & 31) * 4;
        float4 v = *(const float4*)(Cs + r * 132 + c4);
        size_t o = (size_t)(row0 + r) * EMB + col0 + c4;
        if (mode == 0) {
            v.x *= alpha; v.y *= alpha; v.z *= alpha; v.w *= alpha;
            u16 h0,l0,h1,l1,h2,l2,h3,l3;
            split1(v.x,h0,l0); split1(v.y,h1,l1); split1(v.z,h2,l2); split1(v.w,h3,l3);
            *(uint2*)(outH + o) = make_uint2((u32)h0|((u32)h1<<16), (u32)h2|((u32)h3<<16));
            *(uint2*)(outL + o) = make_uint2((u32)l0|((u32)l1<<16), (u32)l2|((u32)l3<<16));
        } else {
            float4 bv = *(const float4*)(bias + col0 + c4);
            v.x += bv.x; v.y += bv.y; v.z += bv.z; v.w += bv.w;
            *(float4*)(outF + o) = v;
        }
    }
}

__global__ __launch_bounds__(256) void qkv_kernel()
{
    int nt = blockIdx.x, sel = nt / 6;
    int col0 = (nt % 6) * 128, row0 = blockIdx.y * 128;
    const u16 *Wh, *Wl; u16 *oh, *ol; float alpha;
    if (sel == 0)      { Wh = g_Wqh; Wl = g_Wql; oh = g_Qh; ol = g_Ql; alpha = 0.125f; }
    else if (sel == 1) { Wh = g_Wkh; Wl = g_Wkl; oh = g_Kh; ol = g_Kl; alpha = 1.f; }
    else               { Wh = g_Wvh; Wl = g_Wvl; oh = g_Vh; ol = g_Vl; alpha = 1.f; }
    gemm128(g_xh, g_xl, Wh, Wl, row0, col0, 0, alpha, oh, ol, nullptr, nullptr);
}

__global__ __launch_bounds__(256) void proj_kernel(float* __restrict__ out,
                                                   const float* __restrict__ bias)
{
    gemm128(g_Oh, g_Ol, g_Woh, g_Wol, blockIdx.y * 128, blockIdx.x * 128,
            1, 1.f, nullptr, nullptr, out, bias);
}

// ---------------------------------------------------------------------------
// 3) V transpose: g_Vh/l [b][s][h*64+d] -> g_Vth/l [bh][d][s]
// ---------------------------------------------------------------------------
__global__ __launch_bounds__(256) void vtrans_kernel()
{
    __shared__ u16 Vh_s[64][GS_PAD], Vl_s[64][GS_PAD];
    int bh = blockIdx.y, b = bh / HEADS, h = bh % HEADS;
    int k0 = blockIdx.x * 64;
    int tid = threadIdx.x;
#pragma unroll
    for (int u = tid; u < 512; u += 256) {
        int row = u >> 3, q = u & 7;
        size_t i = (size_t)(b * SEQ + k0 + row) * EMB + h * 64 + q * 8;
        *(uint4*)(&Vh_s[row][q * 8]) = *(const uint4*)(g_Vh + i);
        *(uint4*)(&Vl_s[row][q * 8]) = *(const uint4*)(g_Vl + i);
    }
    __syncthreads();
#pragma unroll
    for (int u = tid; u < 4096; u += 256) {
        int d = u >> 6, key = u & 63;
        size_t o = ((size_t)bh * DEPTH + d) * SEQ + k0 + key;
        g_Vth[o] = Vh_s[key][d];
        g_Vtl[o] = Vl_s[key][d];
    }
}

// ---------------------------------------------------------------------------
// 4) Flash attention: mma.sync split-3 bf16, 4 warps, 64q x 64k tiles.
//    Warp w owns query rows 16w..16w+15; FA2 fragment softmax.
// ---------------------------------------------------------------------------
#define AP 72
__global__ __launch_bounds__(128) void attn_kernel()
{
    __shared__ __align__(16) u16 smem[4 * 64 * AP];   // 36864 B
    u16* sKh = smem;
    u16* sKl = smem + 64 * AP;
    u16* sVh = smem + 2 * 64 * AP;
    u16* sVl = smem + 3 * 64 * AP;

    const int b = blockIdx.z, h = blockIdx.y, qt = blockIdx.x;
    const int tid = threadIdx.x, warp = tid >> 5, lane = tid & 31;
    const int g = lane >> 2, t = lane & 3;
    const int qr = warp * 16;

    // ---- load Q tile (temp in sK area), extract register fragments ----
#pragma unroll
    for (int u = tid; u < 512; u += 128) {
        int row = u >> 3, q = u & 7;
        size_t i = (size_t)(b * SEQ + qt * 64 + row) * EMB + h * 64 + q * 8;
        *(uint4*)(sKh + row * AP + q * 8) = *(const uint4*)(g_Qh + i);
        *(uint4*)(sKl + row * AP + q * 8) = *(const uint4*)(g_Ql + i);
    }
    __syncthreads();
    u32 qh[4][4], ql[4][4];
#pragma unroll
    for (int k = 0; k < 4; k++) {
        int kk = k * 16 + 2 * t;
        qh[k][0] = *(const u32*)(sKh + (qr + g    ) * AP + kk);
        qh[k][1] = *(const u32*)(sKh + (qr + g + 8) * AP + kk);
        qh[k][2] = *(const u32*)(sKh + (qr + g    ) * AP + kk + 8);
        qh[k][3] = *(const u32*)(sKh + (qr + g + 8) * AP + kk + 8);
        ql[k][0] = *(const u32*)(sKl + (qr + g    ) * AP + kk);
        ql[k][1] = *(const u32*)(sKl + (qr + g + 8) * AP + kk);
        ql[k][2] = *(const u32*)(sKl + (qr + g    ) * AP + kk + 8);
        ql[k][3] = *(const u32*)(sKl + (qr + g + 8) * AP + kk + 8);
    }
    __syncthreads();

    float o[8][4];
#pragma unroll
    for (int d = 0; d < 8; d++)
#pragma unroll
        for (int q = 0; q < 4; q++) o[d][q] = 0.f;
    float m0 = -1e30f, m1 = -1e30f, l0 = 0.f, l1 = 0.f;

    for (int kt = 0; kt < SEQ / 64; kt++) {
        // ---- stage K and V^T tiles ----
#pragma unroll
        for (int u = tid; u < 512; u += 128) {
            int row = u >> 3, q = u & 7;
            size_t ik = (size_t)(b * SEQ + kt * 64 + row) * EMB + h * 64 + q * 8;
            size_t iv = ((size_t)(b * HEADS + h) * DEPTH + row) * SEQ + kt * 64 + q * 8;
            *(uint4*)(sKh + row * AP + q * 8) = *(const uint4*)(g_Kh + ik);
            *(uint4*)(sKl + row * AP + q * 8) = *(const uint4*)(g_Kl + ik);
            *(uint4*)(sVh + row * AP + q * 8) = *(const uint4*)(g_Vth + iv);
            *(uint4*)(sVl + row * AP + q * 8) = *(const uint4*)(g_Vtl + iv);
        }
        __syncthreads();

        // ---- S = (0.125 Q) K^T, split-3 ----
        float S[8][4];
#pragma unroll
        for (int n = 0; n < 8; n++)
#pragma unroll
            for (int q = 0; q < 4; q++) S[n][q] = 0.f;
#pragma unroll
        for (int n = 0; n < 8; n++) {
            int kr = (8 * n + g) * AP;
#pragma unroll
            for (int k = 0; k < 4; k++) {
                int kk = k * 16 + 2 * t;
                u32 bh2[2] = { *(const u32*)(sKh + kr + kk), *(const u32*)(sKh + kr + kk + 8) };
                u32 bl2[2] = { *(const u32*)(sKl + kr + kk), *(const u32*)(sKl + kr + kk + 8) };
                mma16816(S[n], qh[k], bh2);
                mma16816(S[n], qh[k], bl2);
                mma16816(S[n], ql[k], bh2);
            }
        }

        // ---- online softmax on fragments (rows qr+g and qr+g+8) ----
        float mx0 = -1e30f, mx1 = -1e30f;
#pragma unroll
        for (int n = 0; n < 8; n++) {
            mx0 = fmaxf(mx0, fmaxf(S[n][0], S[n][1]));
            mx1 = fmaxf(mx1, fmaxf(S[n][2], S[n][3]));
        }
        mx0 = fmaxf(mx0, __shfl_xor_sync(0xffffffffu, mx0, 1));
        mx0 = fmaxf(mx0, __shfl_xor_sync(0xffffffffu, mx0, 2));
        mx1 = fmaxf(mx1, __shfl_xor_sync(0xffffffffu, mx1, 1));
        mx1 = fmaxf(mx1, __shfl_xor_sync(0xffffffffu, mx1, 2));
        float mn0 = fmaxf(m0, mx0), mn1 = fmaxf(m1, mx1);
        float c0 = __expf(m0 - mn0), c1 = __expf(m1 - mn1);
        float s0 = 0.f, s1 = 0.f;
#pragma unroll
        for (int n = 0; n < 8; n++) {
            S[n][0] = __expf(S[n][0] - mn0); s0 += S[n][0];
            S[n][1] = __expf(S[n][1] - mn0); s0 += S[n][1];
            S[n][2] = __expf(S[n][2] - mn1); s1 += S[n][2];
            S[n][3] = __expf(S[n][3] - mn1); s1 += S[n][3];
        }
        s0 += __shfl_xor_sync(0xffffffffu, s0, 1);
        s0 += __shfl_xor_sync(0xffffffffu, s0, 2);
        s1 += __shfl_xor_sync(0xffffffffu, s1, 1);
        s1 += __shfl_xor_sync(0xffffffffu, s1, 2);
        l0 = l0 * c0 + s0;  l1 = l1 * c1 + s1;
        m0 = mn0;           m1 = mn1;
#pragma unroll
        for (int d = 0; d < 8; d++) {
            o[d][0] *= c0; o[d][1] *= c0; o[d][2] *= c1; o[d][3] *= c1;
        }

        // ---- P (C-fragment layout) -> A fragments, split hi/lo ----
        u32 ph[4][4], pl[4][4];
#pragma unroll
        for (int j = 0; j < 4; j++) {
            split2(S[2*j  ][0], S[2*j  ][1], ph[j][0], pl[j][0]);
            split2(S[2*j  ][2], S[2*j  ][3], ph[j][1], pl[j][1]);
            split2(S[2*j+1][0], S[2*j+1][1], ph[j][2], pl[j][2]);
            split2(S[2*j+1][2], S[2*j+1][3], ph[j][3], pl[j][3]);
        }

        // ---- O += P V, split-3 ----
#pragma unroll
        for (int d = 0; d < 8; d++) {
            int vr = (8 * d + g) * AP;
#pragma unroll
            for (int j = 0; j < 4; j++) {
                int kk = j * 16 + 2 * t;
                u32 bh2[2] = { *(const u32*)(sVh + vr + kk), *(const u32*)(sVh + vr + kk + 8) };
                u32 bl2[2] = { *(const u32*)(sVl + vr + kk), *(const u32*)(sVl + vr + kk + 8) };
                mma16816(o[d], ph[j], bh2);
                mma16816(o[d], ph[j], bl2);
                mma16816(o[d], pl[j], bh2);
            }
        }
        __syncthreads();
    }

    // ---- epilogue: normalize, stage via smem, write split O ----
    float inv0 = 1.f / l0, inv1 = 1.f / l1;
    float* Os = (float*)smem;              // [64][68] fp32 = 17408 B
#pragma unroll
    for (int d = 0; d < 8; d++) {
        int c = 8 * d + 2 * t;
        *(float2*)(Os + (qr + g    ) * 68 + c) = make_float2(o[d][0] * inv0, o[d][1] * inv0);
        *(float2*)(Os + (qr + g + 8) * 68 + c) = make_float2(o[d][2] * inv1, o[d][3] * inv1);
    }
    __syncthreads();
#pragma unroll
    for (int u = tid; u < 4096; u += 128) {
        int r = u >> 6, c = u & 63;
        u16 hh, ll;
        split1(Os[r * 68 + c], hh, ll);
        size_t i = (size_t)(b * SEQ + qt * 64 + r) * EMB + h * 64 + c;
        g_Oh[i] = hh; g_Ol[i] = ll;
    }
}

// ---------------------------------------------------------------------------
extern "C" void kernel_launch(void* const* d_in, const int* in_sizes, int n_in,
                              void* d_out, int out_size)
{
    const float* x  = (const float*)d_in[0];
    const float* Wq = (const float*)d_in[1];
    const float* Wk = (const float*)d_in[2];
    const float* Wv = (const float*)d_in[3];
    const float* Wo = (const float*)d_in[4];
    const float* bo = (const float*)d_in[5];
    float* out = (float*)d_out;

    cudaFuncSetAttribute(qkv_kernel,
                         cudaFuncAttributeMaxDynamicSharedMemorySize, GEMM_SMEM_BYTES);
    cudaFuncSetAttribute(proj_kernel,
                         cudaFuncAttributeMaxDynamicSharedMemorySize, GEMM_SMEM_BYTES);

    u16 *xh, *xl;
    cudaGetSymbolAddress((void**)&xh, g_xh);
    cudaGetSymbolAddress((void**)&xl, g_xl);

    // 1) split-convert inputs (x + all four weights in one fused launch)
    convert_kernel<<<(MROWS * EMB) / 1024, 256>>>(x, xh, xl, MROWS * EMB);
    convert_w_kernel<<<dim3((EMB * EMB) / 1024, 4), 256>>>(Wq, Wk, Wv, Wo);

    // 2) QKV projections
    qkv_kernel<<<dim3(18, 64), 256, GEMM_SMEM_BYTES>>>();

    // 3) V transpose
    vtrans_kernel<<<dim3(SEQ / 64, BH), 256>>>();

    // 4) flash attention
    attn_kernel<<<dim3(SEQ / 64, HEADS, BATCH), 128>>>();

    // 5) output projection + bias
    proj_kernel<<<dim3(6, 64), 256, GEMM_SMEM_BYTES>>>(out, bo);
}